// round 2
// baseline (speedup 1.0000x reference)
#include <cuda_runtime.h>
#include <cstdint>
#include <cstddef>

#define IN_DIM   512
#define HID      256
#define BM       64
#define BN       256
#define BK       32
#define NTHREADS 256

// per-node scalar s[n] = relu(emb[n] @ W + b) . w_sym   (N = 50000, padded)
__device__ float g_s[50176];

struct SmemLayout {
    unsigned As[2][BK][BM + 4];   // tf32 bits, [k][m] (transposed for frag loads)
    unsigned Bs[2][BK][BN + 4];   // tf32 bits, [k][n]
    float    bb[BN];              // b_emb
    float    bw[BN];              // w_sym
    float    red[BM];             // cross-warp reduction
};

__device__ __forceinline__ unsigned f2tf(float x) {
    unsigned r;
    asm("cvt.rna.tf32.f32 %0, %1;" : "=r"(r) : "f"(x));
    return r;
}

__device__ __forceinline__ void mma8(float* c,
                                     unsigned a0, unsigned a1, unsigned a2, unsigned a3,
                                     unsigned b0, unsigned b1) {
    asm volatile(
        "mma.sync.aligned.m16n8k8.row.col.f32.tf32.tf32.f32 "
        "{%0,%1,%2,%3}, {%4,%5,%6,%7}, {%8,%9}, {%0,%1,%2,%3};"
        : "+f"(c[0]), "+f"(c[1]), "+f"(c[2]), "+f"(c[3])
        : "r"(a0), "r"(a1), "r"(a2), "r"(a3), "r"(b0), "r"(b1));
}

__global__ void node_kernel(const float* __restrict__ emb,
                            const float* __restrict__ W,
                            const float* __restrict__ bias,
                            const float* __restrict__ We,
                            int nn) {
    extern __shared__ char smraw[];
    SmemLayout& sm = *reinterpret_cast<SmemLayout*>(smraw);

    const int tid  = threadIdx.x;
    const int lane = tid & 31;
    const int wid  = tid >> 5;
    const int wr   = wid >> 1;   // 0..3  (16 rows each)
    const int wc   = wid & 1;    // 0..1  (128 cols each)
    const int row0 = blockIdx.x * BM;

    if (tid < BN) {
        sm.bb[tid] = bias[tid];
        sm.bw[tid] = 0.5f * (We[tid] + We[tid + HID]);
    }

    float4 ra[2];
    float4 rb[8];

    auto loadA = [&](int kt) {
        const int k0 = kt * BK;
        #pragma unroll
        for (int i = 0; i < 2; ++i) {
            int f = tid + i * NTHREADS;
            int r = f >> 3, c4 = f & 7;
            int gr = row0 + r;
            if (gr < nn)
                ra[i] = *reinterpret_cast<const float4*>(&emb[(size_t)gr * IN_DIM + k0 + c4 * 4]);
            else
                ra[i] = make_float4(0.f, 0.f, 0.f, 0.f);
        }
    };
    auto loadB = [&](int kt) {
        const int k0 = kt * BK;
        #pragma unroll
        for (int i = 0; i < 8; ++i) {
            int f = tid + i * NTHREADS;
            int r = f >> 6, c4 = f & 63;
            rb[i] = *reinterpret_cast<const float4*>(&W[(size_t)(k0 + r) * HID + c4 * 4]);
        }
    };
    auto storeTiles = [&](int buf) {
        #pragma unroll
        for (int i = 0; i < 2; ++i) {
            int f = tid + i * NTHREADS;
            int r = f >> 3, c4 = f & 7;
            sm.As[buf][c4 * 4 + 0][r] = f2tf(ra[i].x);
            sm.As[buf][c4 * 4 + 1][r] = f2tf(ra[i].y);
            sm.As[buf][c4 * 4 + 2][r] = f2tf(ra[i].z);
            sm.As[buf][c4 * 4 + 3][r] = f2tf(ra[i].w);
        }
        #pragma unroll
        for (int i = 0; i < 8; ++i) {
            int f = tid + i * NTHREADS;
            int r = f >> 6, c4 = f & 63;
            uint4 v;
            v.x = f2tf(rb[i].x); v.y = f2tf(rb[i].y);
            v.z = f2tf(rb[i].z); v.w = f2tf(rb[i].w);
            *reinterpret_cast<uint4*>(&sm.Bs[buf][r][c4 * 4]) = v;
        }
    };

    float acc[16][4];
    #pragma unroll
    for (int t = 0; t < 16; ++t)
        acc[t][0] = acc[t][1] = acc[t][2] = acc[t][3] = 0.f;

    const int tg = lane & 3;   // thread-in-group (k / col-pair index)
    const int gp = lane >> 2;  // group id (row / col index)

    loadA(0); loadB(0);
    storeTiles(0);
    loadA(1); loadB(1);
    __syncthreads();

    const int NKT = IN_DIM / BK;  // 16
    #pragma unroll 1
    for (int kt = 0; kt < NKT; ++kt) {
        const int buf = kt & 1;
        #pragma unroll
        for (int ks = 0; ks < 4; ++ks) {
            const int kb = ks * 8;
            unsigned a0 = sm.As[buf][kb + tg    ][wr * 16 + gp    ];
            unsigned a1 = sm.As[buf][kb + tg    ][wr * 16 + gp + 8];
            unsigned a2 = sm.As[buf][kb + tg + 4][wr * 16 + gp    ];
            unsigned a3 = sm.As[buf][kb + tg + 4][wr * 16 + gp + 8];
            #pragma unroll
            for (int tj = 0; tj < 16; ++tj) {
                const int col = wc * 128 + tj * 8 + gp;
                unsigned b0 = sm.Bs[buf][kb + tg    ][col];
                unsigned b1 = sm.Bs[buf][kb + tg + 4][col];
                mma8(acc[tj], a0, a1, a2, a3, b0, b1);
            }
        }
        if (kt < NKT - 1) {
            storeTiles((kt + 1) & 1);            // buffer kt+1: last read at kt-1, safe
            if (kt < NKT - 2) { loadA(kt + 2); loadB(kt + 2); }
            __syncthreads();
        }
    }

    // epilogue: relu(acc + b) * w_sym, reduce over the 256 columns -> s[row]
    float p0 = 0.f, p1 = 0.f;
    #pragma unroll
    for (int tj = 0; tj < 16; ++tj) {
        const int col = wc * 128 + tj * 8 + tg * 2;
        const float w0 = sm.bw[col], w1 = sm.bw[col + 1];
        const float b0f = sm.bb[col], b1f = sm.bb[col + 1];
        p0 += fmaxf(acc[tj][0] + b0f, 0.f) * w0 + fmaxf(acc[tj][1] + b1f, 0.f) * w1;
        p1 += fmaxf(acc[tj][2] + b0f, 0.f) * w0 + fmaxf(acc[tj][3] + b1f, 0.f) * w1;
    }
    // reduce across the 4 lanes of each row group
    p0 += __shfl_xor_sync(0xffffffffu, p0, 1);
    p0 += __shfl_xor_sync(0xffffffffu, p0, 2);
    p1 += __shfl_xor_sync(0xffffffffu, p1, 1);
    p1 += __shfl_xor_sync(0xffffffffu, p1, 2);

    if (wc == 0 && tg == 0) {
        sm.red[wr * 16 + gp    ] = p0;
        sm.red[wr * 16 + gp + 8] = p1;
    }
    __syncthreads();
    if (wc == 1 && tg == 0) {
        const int lr = wr * 16 + gp;
        const int gr0 = row0 + lr, gr1 = gr0 + 8;
        if (gr0 < nn) g_s[gr0] = sm.red[lr    ] + p0;
        if (gr1 < nn) g_s[gr1] = sm.red[lr + 8] + p1;
    }
}

__global__ void edge_kernel(const int* __restrict__ e0,
                            const int* __restrict__ e1,
                            const float* __restrict__ u,
                            const float* __restrict__ be,
                            float* __restrict__ out,
                            int E) {
    const int i = blockIdx.x * blockDim.x + threadIdx.x;
    if (i >= E) return;
    const int a = e0[i];
    const int b = e1[i];
    const float raw = g_s[a] + g_s[b] + be[0];
    const float uu = u[i];
    // eps = (BIAS - (1-BIAS))*u + (1-BIAS),  BIAS = 1e-4
    const float eps = fmaf(-0.9998f, uu, 0.9999f);
    const float gate = logf(eps) - log1pf(-eps) + raw;
    out[i] = 1.0f / (1.0f + expf(-gate));
}

extern "C" void kernel_launch(void* const* d_in, const int* in_sizes, int n_in,
                              void* d_out, int out_size) {
    const float* emb   = (const float*)d_in[0];
    const int*   edges = (const int*)d_in[1];     // int32! (JAX x64 disabled)
    const float* u     = (const float*)d_in[2];
    const float* W     = (const float*)d_in[3];
    const float* b     = (const float*)d_in[4];
    const float* We    = (const float*)d_in[5];
    const float* be    = (const float*)d_in[6];
    float*       out   = (float*)d_out;

    const int nn = in_sizes[0] / IN_DIM;   // 50000
    const int E  = in_sizes[2];            // 800000 (in_sizes[1] == 2*E)

    const int smem = (int)sizeof(SmemLayout);
    cudaFuncSetAttribute(node_kernel, cudaFuncAttributeMaxDynamicSharedMemorySize, smem);

    node_kernel<<<(nn + BM - 1) / BM, NTHREADS, smem>>>(emb, W, b, We, nn);
    edge_kernel<<<(E + 255) / 256, 256>>>(edges, edges + E, u, be, out, E);
}

// round 4
// speedup vs baseline: 2.0493x; 2.0493x over previous
#include <cuda_runtime.h>
#include <cuda_bf16.h>
#include <cstdint>
#include <cstddef>

#define IN_DIM   512
#define HID      256
#define BM       128
#define KB       64      // K per stage
#define NS       8       // IN_DIM / KB
#define NTHREADS 256

// per-node scalar s[n] = relu(emb[n] @ W + b) . w_sym
__device__ float g_s[50176];
// W pre-converted to bf16, same [IN_DIM][HID] layout
__device__ __nv_bfloat16 g_Wb[IN_DIM * HID];

// ---- smem layout (bytes) ----
#define OFF_A      0          // 2 x (128 rows x 128B)  = 32768
#define OFF_B      32768      // 3 x (64 rows x 512B)   = 98304
#define OFF_BW     131072     // float2[256]            = 2048
#define OFF_RED    133120     // float[128]             = 512
#define SMEM_TOTAL 133632

__device__ __forceinline__ uint32_t smem_u32(const void* p) {
    uint32_t a;
    asm("{ .reg .u64 t; cvta.to.shared.u64 t, %1; cvt.u32.u64 %0, t; }" : "=r"(a) : "l"(p));
    return a;
}
__device__ __forceinline__ void ldsm_x4(uint32_t* r, uint32_t addr) {
    asm volatile("ldmatrix.sync.aligned.m8n8.x4.shared.b16 {%0,%1,%2,%3}, [%4];"
                 : "=r"(r[0]), "=r"(r[1]), "=r"(r[2]), "=r"(r[3]) : "r"(addr));
}
__device__ __forceinline__ void ldsm_x4t(uint32_t* r, uint32_t addr) {
    asm volatile("ldmatrix.sync.aligned.m8n8.x4.trans.shared.b16 {%0,%1,%2,%3}, [%4];"
                 : "=r"(r[0]), "=r"(r[1]), "=r"(r[2]), "=r"(r[3]) : "r"(addr));
}
__device__ __forceinline__ void mma16816(float* c, const uint32_t* a, uint32_t b0, uint32_t b1) {
    asm volatile(
        "mma.sync.aligned.m16n8k16.row.col.f32.bf16.bf16.f32 "
        "{%0,%1,%2,%3}, {%4,%5,%6,%7}, {%8,%9}, {%0,%1,%2,%3};"
        : "+f"(c[0]), "+f"(c[1]), "+f"(c[2]), "+f"(c[3])
        : "r"(a[0]), "r"(a[1]), "r"(a[2]), "r"(a[3]), "r"(b0), "r"(b1));
}
__device__ __forceinline__ void cp16(uint32_t dst, const void* src) {
    asm volatile("cp.async.cg.shared.global [%0], [%1], 16;" :: "r"(dst), "l"(src));
}
#define CP_COMMIT() asm volatile("cp.async.commit_group;" ::: "memory")
#define CP_WAIT(N)  asm volatile("cp.async.wait_group %0;" :: "n"(N) : "memory")

__device__ __forceinline__ uint32_t pack_bf2(float lo, float hi) {
    return (uint32_t)__bfloat16_as_ushort(__float2bfloat16_rn(hi)) << 16
         | (uint32_t)__bfloat16_as_ushort(__float2bfloat16_rn(lo));
}

__global__ void convert_W(const float* __restrict__ W) {
    const int i = blockIdx.x * blockDim.x + threadIdx.x;
    if (i < IN_DIM * HID) g_Wb[i] = __float2bfloat16_rn(W[i]);
}

__global__ void __launch_bounds__(NTHREADS, 1)
node_kernel(const float* __restrict__ emb,
            const float* __restrict__ bias,
            const float* __restrict__ We,
            int nn) {
    extern __shared__ char smraw[];
    const uint32_t smem = smem_u32(smraw);
    const int tid  = threadIdx.x;
    const int lane = tid & 31;
    const int wid  = tid >> 5;
    const int wm   = wid >> 2;     // 0..1  -> rows wm*64..
    const int wn   = wid & 3;      // 0..3  -> cols wn*64..
    const int row0 = blockIdx.x * BM;

    if (tid < 128) *reinterpret_cast<float*>(smraw + OFF_RED + tid * 4) = 0.f;
    {
        float2 v; v.x = bias[tid]; v.y = 0.5f * (We[tid] + We[tid + HID]);
        *reinterpret_cast<float2*>(smraw + OFF_BW + tid * 8) = v;
    }

    // ---- stage loaders ----
    float4 ra[4][2];   // A staging: 4 chunks x 8 floats

    auto loadA = [&](int s) {
        #pragma unroll
        for (int i = 0; i < 4; ++i) {
            const int flat = tid + i * NTHREADS;       // 0..1023
            const int m = flat >> 3, c = flat & 7;     // row, 8-elem chunk
            const int gr = row0 + m;
            if (gr < nn) {
                const float* p = &emb[(size_t)gr * IN_DIM + s * KB + c * 8];
                ra[i][0] = *reinterpret_cast<const float4*>(p);
                ra[i][1] = *reinterpret_cast<const float4*>(p + 4);
            } else {
                ra[i][0] = make_float4(0.f, 0.f, 0.f, 0.f);
                ra[i][1] = make_float4(0.f, 0.f, 0.f, 0.f);
            }
        }
    };
    auto stsA = [&](int buf) {
        #pragma unroll
        for (int i = 0; i < 4; ++i) {
            const int flat = tid + i * NTHREADS;
            const int m = flat >> 3, c = flat & 7;
            uint4 t;
            t.x = pack_bf2(ra[i][0].x, ra[i][0].y);
            t.y = pack_bf2(ra[i][0].z, ra[i][0].w);
            t.z = pack_bf2(ra[i][1].x, ra[i][1].y);
            t.w = pack_bf2(ra[i][1].z, ra[i][1].w);
            const uint32_t off = OFF_A + buf * 16384 + m * 128 + ((c ^ (m & 7)) << 4);
            *reinterpret_cast<uint4*>(smraw + off) = t;
        }
    };
    auto cpB = [&](int s, int buf) {
        #pragma unroll
        for (int i = 0; i < 8; ++i) {
            const int flat = tid + i * NTHREADS;       // 0..2047
            const int kr = flat >> 5, ch = flat & 31;  // k-row, 8-elem chunk
            const uint32_t dst = smem + OFF_B + buf * 32768 + kr * 512 + ((ch ^ (kr & 7)) << 4);
            cp16(dst, &g_Wb[(size_t)(s * KB + kr) * HID + ch * 8]);
        }
        CP_COMMIT();
    };

    float acc[4][8][4];
    #pragma unroll
    for (int i = 0; i < 4; ++i)
        #pragma unroll
        for (int j = 0; j < 8; ++j)
            acc[i][j][0] = acc[i][j][1] = acc[i][j][2] = acc[i][j][3] = 0.f;

    // ---- prologue ----
    loadA(0); stsA(0);
    cpB(0, 0);
    cpB(1, 1);
    loadA(1);
    CP_WAIT(1);          // B(0) complete
    __syncthreads();

    const int lr  = (lane & 7) + (lane & 8);   // ldmatrix row-within-pair
    const int lhi = (lane >> 4) & 1;           // second 8-chunk select

    #pragma unroll 1
    for (int s = 0; s < NS; ++s) {
        if (s + 2 < NS) cpB(s + 2, (s + 2) % 3);
        if (s + 1 < NS) stsA((s + 1) & 1);
        if (s + 2 < NS) loadA(s + 2);

        const uint32_t aBase = smem + OFF_A + (s & 1) * 16384;
        const uint32_t bBase = smem + OFF_B + (s % 3) * 32768;

        #pragma unroll
        for (int kk = 0; kk < 4; ++kk) {
            const int k0 = kk * 16;
            uint32_t a[4][4];
            #pragma unroll
            for (int i = 0; i < 4; ++i) {
                const int mr = wm * 64 + i * 16 + lr;
                const int kc = (k0 >> 3) + lhi;
                ldsm_x4(a[i], aBase + mr * 128 + ((kc ^ (mr & 7)) << 4));
            }
            uint32_t b[4][4];
            #pragma unroll
            for (int j = 0; j < 4; ++j) {
                const int kr = k0 + lr;
                const int nc = wn * 8 + j * 2 + lhi;
                ldsm_x4t(b[j], bBase + kr * 512 + ((nc ^ (kr & 7)) << 4));
            }
            #pragma unroll
            for (int i = 0; i < 4; ++i)
                #pragma unroll
                for (int j = 0; j < 4; ++j) {
                    mma16816(acc[i][j * 2 + 0], a[i], b[j][0], b[j][1]);
                    mma16816(acc[i][j * 2 + 1], a[i], b[j][2], b[j][3]);
                }
        }

        if (s + 1 < NS) {
            if (s + 2 < NS) { CP_WAIT(1); } else { CP_WAIT(0); }
            __syncthreads();
        }
    }

    // ---- epilogue: p[m] = sum_n relu(D[m][n]+bias[n])*w_sym[n] ----
    const float2* bw = reinterpret_cast<const float2*>(smraw + OFF_BW);
    float* red = reinterpret_cast<float*>(smraw + OFF_RED);
    #pragma unroll
    for (int i = 0; i < 4; ++i) {
        float p0 = 0.f, p1 = 0.f;
        #pragma unroll
        for (int t = 0; t < 8; ++t) {
            const int ncol = wn * 64 + t * 8 + (lane & 3) * 2;
            const float2 w0 = bw[ncol], w1 = bw[ncol + 1];
            const float* c = acc[i][t];
            p0 += fmaxf(c[0] + w0.x, 0.f) * w0.y + fmaxf(c[1] + w1.x, 0.f) * w1.y;
            p1 += fmaxf(c[2] + w0.x, 0.f) * w0.y + fmaxf(c[3] + w1.x, 0.f) * w1.y;
        }
        p0 += __shfl_xor_sync(0xffffffffu, p0, 1);
        p0 += __shfl_xor_sync(0xffffffffu, p0, 2);
        p1 += __shfl_xor_sync(0xffffffffu, p1, 1);
        p1 += __shfl_xor_sync(0xffffffffu, p1, 2);
        if ((lane & 3) == 0) {
            const int r = wm * 64 + i * 16 + (lane >> 2);
            atomicAdd(&red[r], p0);
            atomicAdd(&red[r + 8], p1);
        }
    }
    __syncthreads();
    if (tid < BM) {
        const int gr = row0 + tid;
        if (gr < nn) g_s[gr] = red[tid];
    }
}

// sigmoid(log(eps/(1-eps)) + raw) == eps / (eps + (1-eps)*exp(-raw))
__global__ void edge_kernel(const int* __restrict__ e0,
                            const int* __restrict__ e1,
                            const float* __restrict__ u,
                            const float* __restrict__ be,
                            float* __restrict__ out,
                            int E) {
    const int i = blockIdx.x * blockDim.x + threadIdx.x;
    const int nv = E >> 2;
    if (i >= nv) {
        if (i == nv) {
            const float bb = be[0];
            for (int k = nv * 4; k < E; ++k) {
                const float raw = g_s[e0[k]] + g_s[e1[k]] + bb;
                const float uu = u[k];
                const float eps = fmaf(-0.9998f, uu, 0.9999f);
                const float ome = fmaf(0.9998f, uu, 0.0001f);
                out[k] = eps / fmaf(ome, __expf(-raw), eps);
            }
        }
        return;
    }
    const int4   a  = reinterpret_cast<const int4*>(e0)[i];
    const int4   b  = reinterpret_cast<const int4*>(e1)[i];
    const float4 uu = reinterpret_cast<const float4*>(u)[i];
    const float  bb = be[0];
    float4 r;
    {
        const float raw = g_s[a.x] + g_s[b.x] + bb;
        const float eps = fmaf(-0.9998f, uu.x, 0.9999f);
        const float ome = fmaf(0.9998f, uu.x, 0.0001f);
        r.x = eps / fmaf(ome, __expf(-raw), eps);
    }
    {
        const float raw = g_s[a.y] + g_s[b.y] + bb;
        const float eps = fmaf(-0.9998f, uu.y, 0.9999f);
        const float ome = fmaf(0.9998f, uu.y, 0.0001f);
        r.y = eps / fmaf(ome, __expf(-raw), eps);
    }
    {
        const float raw = g_s[a.z] + g_s[b.z] + bb;
        const float eps = fmaf(-0.9998f, uu.z, 0.9999f);
        const float ome = fmaf(0.9998f, uu.z, 0.0001f);
        r.z = eps / fmaf(ome, __expf(-raw), eps);
    }
    {
        const float raw = g_s[a.w] + g_s[b.w] + bb;
        const float eps = fmaf(-0.9998f, uu.w, 0.9999f);
        const float ome = fmaf(0.9998f, uu.w, 0.0001f);
        r.w = eps / fmaf(ome, __expf(-raw), eps);
    }
    reinterpret_cast<float4*>(out)[i] = r;
}

extern "C" void kernel_launch(void* const* d_in, const int* in_sizes, int n_in,
                              void* d_out, int out_size) {
    const float* emb   = (const float*)d_in[0];
    const int*   edges = (const int*)d_in[1];     // int32 (JAX x64 disabled)
    const float* u     = (const float*)d_in[2];
    const float* W     = (const float*)d_in[3];
    const float* b     = (const float*)d_in[4];
    const float* We    = (const float*)d_in[5];
    const float* be    = (const float*)d_in[6];
    float*       out   = (float*)d_out;

    const int nn = in_sizes[0] / IN_DIM;   // 50000
    const int E  = in_sizes[2];            // 800000

    convert_W<<<(IN_DIM * HID + 255) / 256, 256>>>(W);

    cudaFuncSetAttribute(node_kernel, cudaFuncAttributeMaxDynamicSharedMemorySize, SMEM_TOTAL);
    node_kernel<<<(nn + BM - 1) / BM, NTHREADS, SMEM_TOTAL>>>(emb, b, We, nn);

    const int nv = (E >> 2) + 1;
    edge_kernel<<<(nv + 255) / 256, 256>>>(edges, edges + E, u, be, out, E);
}

// round 7
// speedup vs baseline: 2.6172x; 1.2772x over previous
#include <cuda_runtime.h>
#include <cuda_bf16.h>
#include <cstdint>
#include <cstddef>

#define IN_DIM   512
#define HID      256
#define BM       128
#define KB       64      // K per stage
#define NS       8       // IN_DIM / KB
#define NTHREADS 512

// per-node scalar s[n] = relu(emb[n] @ W + b) . w_sym
__device__ float g_s[50176];
// W pre-converted to bf16, same [IN_DIM][HID] layout
__device__ __nv_bfloat16 g_Wb[IN_DIM * HID];

// ---- smem layout (bytes) ----
#define OFF_A      0          // 2 x (128 rows x 128B)  = 32768
#define OFF_B      32768      // 3 x (64 rows x 512B)   = 98304
#define OFF_BW     131072     // float2[256]            = 2048
#define OFF_RED    133120     // float[128]             = 512
#define SMEM_TOTAL 133632

__device__ __forceinline__ uint32_t smem_u32(const void* p) {
    uint32_t a;
    asm("{ .reg .u64 t; cvta.to.shared.u64 t, %1; cvt.u32.u64 %0, t; }" : "=r"(a) : "l"(p));
    return a;
}
__device__ __forceinline__ void ldsm_x4(uint32_t* r, uint32_t addr) {
    asm volatile("ldmatrix.sync.aligned.m8n8.x4.shared.b16 {%0,%1,%2,%3}, [%4];"
                 : "=r"(r[0]), "=r"(r[1]), "=r"(r[2]), "=r"(r[3]) : "r"(addr));
}
__device__ __forceinline__ void ldsm_x4t(uint32_t* r, uint32_t addr) {
    asm volatile("ldmatrix.sync.aligned.m8n8.x4.trans.shared.b16 {%0,%1,%2,%3}, [%4];"
                 : "=r"(r[0]), "=r"(r[1]), "=r"(r[2]), "=r"(r[3]) : "r"(addr));
}
__device__ __forceinline__ void mma16816(float* c, const uint32_t* a, uint32_t b0, uint32_t b1) {
    asm volatile(
        "mma.sync.aligned.m16n8k16.row.col.f32.bf16.bf16.f32 "
        "{%0,%1,%2,%3}, {%4,%5,%6,%7}, {%8,%9}, {%0,%1,%2,%3};"
        : "+f"(c[0]), "+f"(c[1]), "+f"(c[2]), "+f"(c[3])
        : "r"(a[0]), "r"(a[1]), "r"(a[2]), "r"(a[3]), "r"(b0), "r"(b1));
}
__device__ __forceinline__ void cp16(uint32_t dst, const void* src) {
    asm volatile("cp.async.cg.shared.global [%0], [%1], 16;" :: "r"(dst), "l"(src));
}
#define CP_COMMIT() asm volatile("cp.async.commit_group;" ::: "memory")
#define CP_WAIT(N)  asm volatile("cp.async.wait_group %0;" :: "n"(N) : "memory")

__device__ __forceinline__ uint32_t pack_bf2(float lo, float hi) {
    return (uint32_t)__bfloat16_as_ushort(__float2bfloat16_rn(hi)) << 16
         | (uint32_t)__bfloat16_as_ushort(__float2bfloat16_rn(lo));
}

__global__ void convert_W(const float4* __restrict__ W4) {
    const int i = blockIdx.x * blockDim.x + threadIdx.x;
    if (i < IN_DIM * HID / 4) {
        const float4 v = W4[i];
        uint2 o;
        o.x = pack_bf2(v.x, v.y);
        o.y = pack_bf2(v.z, v.w);
        *reinterpret_cast<uint2*>(&g_Wb[i * 4]) = o;
    }
}

__global__ void __launch_bounds__(NTHREADS, 1)
node_kernel(const float* __restrict__ emb,
            const float* __restrict__ bias,
            const float* __restrict__ We,
            int nn) {
    extern __shared__ char smraw[];
    const uint32_t smem = smem_u32(smraw);
    const int tid  = threadIdx.x;
    const int lane = tid & 31;
    const int wid  = tid >> 5;     // 0..15
    const int wm   = wid >> 2;     // 0..3  -> rows wm*32..
    const int wn   = wid & 3;      // 0..3  -> cols wn*64..
    const int row0 = blockIdx.x * BM;

    if (tid < 128) *reinterpret_cast<float*>(smraw + OFF_RED + tid * 4) = 0.f;
    if (tid < 256) {
        float2 v; v.x = bias[tid]; v.y = 0.5f * (We[tid] + We[tid + HID]);
        *reinterpret_cast<float2*>(smraw + OFF_BW + tid * 8) = v;
    }

    // ---- stage loaders ----
    float4 ra[2][2];   // A staging: 2 chunks x 8 floats

    auto loadA = [&](int s) {
        #pragma unroll
        for (int i = 0; i < 2; ++i) {
            const int flat = tid + i * NTHREADS;       // 0..1023
            const int m = flat >> 3, c = flat & 7;     // row, 8-elem chunk
            const int gr = row0 + m;
            if (gr < nn) {
                const float* p = &emb[(size_t)gr * IN_DIM + s * KB + c * 8];
                ra[i][0] = *reinterpret_cast<const float4*>(p);
                ra[i][1] = *reinterpret_cast<const float4*>(p + 4);
            } else {
                ra[i][0] = make_float4(0.f, 0.f, 0.f, 0.f);
                ra[i][1] = make_float4(0.f, 0.f, 0.f, 0.f);
            }
        }
    };
    auto stsA = [&](int buf) {
        #pragma unroll
        for (int i = 0; i < 2; ++i) {
            const int flat = tid + i * NTHREADS;
            const int m = flat >> 3, c = flat & 7;
            uint4 t;
            t.x = pack_bf2(ra[i][0].x, ra[i][0].y);
            t.y = pack_bf2(ra[i][0].z, ra[i][0].w);
            t.z = pack_bf2(ra[i][1].x, ra[i][1].y);
            t.w = pack_bf2(ra[i][1].z, ra[i][1].w);
            const uint32_t off = OFF_A + buf * 16384 + m * 128 + ((c ^ (m & 7)) << 4);
            *reinterpret_cast<uint4*>(smraw + off) = t;
        }
    };
    auto cpB = [&](int s, int buf) {
        #pragma unroll
        for (int i = 0; i < 4; ++i) {
            const int flat = tid + i * NTHREADS;       // 0..2047
            const int kr = flat >> 5, ch = flat & 31;  // k-row, 8-elem chunk
            const uint32_t dst = smem + OFF_B + buf * 32768 + kr * 512 + ((ch ^ (kr & 7)) << 4);
            cp16(dst, &g_Wb[(size_t)(s * KB + kr) * HID + ch * 8]);
        }
        CP_COMMIT();
    };

    float acc[2][8][4];
    #pragma unroll
    for (int i = 0; i < 2; ++i)
        #pragma unroll
        for (int j = 0; j < 8; ++j)
            acc[i][j][0] = acc[i][j][1] = acc[i][j][2] = acc[i][j][3] = 0.f;

    // ---- prologue ----
    loadA(0); stsA(0);
    cpB(0, 0);
    cpB(1, 1);
    loadA(1);
    CP_WAIT(1);          // B(0) complete
    __syncthreads();

    const int lr  = (lane & 7) + (lane & 8);   // ldmatrix row-within-pair
    const int lhi = (lane >> 4) & 1;           // second 8-chunk select

    #pragma unroll 1
    for (int s = 0; s < NS; ++s) {
        if (s + 2 < NS) cpB(s + 2, (s + 2) % 3);
        if (s + 1 < NS) stsA((s + 1) & 1);
        if (s + 2 < NS) loadA(s + 2);

        const uint32_t aBase = smem + OFF_A + (s & 1) * 16384;
        const uint32_t bBase = smem + OFF_B + (s % 3) * 32768;

        #pragma unroll
        for (int kk = 0; kk < 4; ++kk) {
            const int k0 = kk * 16;
            uint32_t a[2][4];
            #pragma unroll
            for (int i = 0; i < 2; ++i) {
                const int mr = wm * 32 + i * 16 + lr;
                const int kc = (k0 >> 3) + lhi;
                ldsm_x4(a[i], aBase + mr * 128 + ((kc ^ (mr & 7)) << 4));
            }
            uint32_t b[4][4];
            #pragma unroll
            for (int j = 0; j < 4; ++j) {
                const int kr = k0 + lr;
                const int nc = wn * 8 + j * 2 + lhi;
                ldsm_x4t(b[j], bBase + kr * 512 + ((nc ^ (kr & 7)) << 4));
            }
            #pragma unroll
            for (int i = 0; i < 2; ++i)
                #pragma unroll
                for (int j = 0; j < 4; ++j) {
                    mma16816(acc[i][j * 2 + 0], a[i], b[j][0], b[j][1]);
                    mma16816(acc[i][j * 2 + 1], a[i], b[j][2], b[j][3]);
                }
        }

        if (s + 1 < NS) {
            if (s + 2 < NS) { CP_WAIT(1); } else { CP_WAIT(0); }
            __syncthreads();
        }
    }

    // ---- epilogue: p[m] = sum_n relu(D[m][n]+bias[n])*w_sym[n] ----
    const float2* bw = reinterpret_cast<const float2*>(smraw + OFF_BW);
    float* red = reinterpret_cast<float*>(smraw + OFF_RED);
    #pragma unroll
    for (int i = 0; i < 2; ++i) {
        float p0 = 0.f, p1 = 0.f;
        #pragma unroll
        for (int t = 0; t < 8; ++t) {
            const int ncol = wn * 64 + t * 8 + (lane & 3) * 2;
            const float2 w0 = bw[ncol], w1 = bw[ncol + 1];
            const float* c = acc[i][t];
            p0 += fmaxf(c[0] + w0.x, 0.f) * w0.y + fmaxf(c[1] + w1.x, 0.f) * w1.y;
            p1 += fmaxf(c[2] + w0.x, 0.f) * w0.y + fmaxf(c[3] + w1.x, 0.f) * w1.y;
        }
        p0 += __shfl_xor_sync(0xffffffffu, p0, 1);
        p0 += __shfl_xor_sync(0xffffffffu, p0, 2);
        p1 += __shfl_xor_sync(0xffffffffu, p1, 1);
        p1 += __shfl_xor_sync(0xffffffffu, p1, 2);
        if ((lane & 3) == 0) {
            const int r = wm * 32 + i * 16 + (lane >> 2);
            atomicAdd(&red[r], p0);
            atomicAdd(&red[r + 8], p1);
        }
    }
    __syncthreads();
    if (tid < BM) {
        const int gr = row0 + tid;
        if (gr < nn) g_s[gr] = red[tid];
    }
}

// sigmoid(log(eps/(1-eps)) + raw) == eps / (eps + (1-eps)*exp(-raw))
__global__ void edge_kernel(const int* __restrict__ e0,
                            const int* __restrict__ e1,
                            const float* __restrict__ u,
                            const float* __restrict__ be,
                            float* __restrict__ out,
                            int E) {
    const int i = blockIdx.x * blockDim.x + threadIdx.x;
    const int nv = E >> 2;
    if (i >= nv) {
        if (i == nv) {
            const float bb = be[0];
            for (int k = nv * 4; k < E; ++k) {
                const float raw = g_s[e0[k]] + g_s[e1[k]] + bb;
                const float uu = u[k];
                const float eps = fmaf(-0.9998f, uu, 0.9999f);
                const float ome = fmaf(0.9998f, uu, 0.0001f);
                out[k] = eps / fmaf(ome, __expf(-raw), eps);
            }
        }
        return;
    }
    const int4   a  = reinterpret_cast<const int4*>(e0)[i];
    const int4   b  = reinterpret_cast<const int4*>(e1)[i];
    const float4 uu = reinterpret_cast<const float4*>(u)[i];
    const float  bb = be[0];
    float4 r;
    {
        const float raw = g_s[a.x] + g_s[b.x] + bb;
        const float eps = fmaf(-0.9998f, uu.x, 0.9999f);
        const float ome = fmaf(0.9998f, uu.x, 0.0001f);
        r.x = eps / fmaf(ome, __expf(-raw), eps);
    }
    {
        const float raw = g_s[a.y] + g_s[b.y] + bb;
        const float eps = fmaf(-0.9998f, uu.y, 0.9999f);
        const float ome = fmaf(0.9998f, uu.y, 0.0001f);
        r.y = eps / fmaf(ome, __expf(-raw), eps);
    }
    {
        const float raw = g_s[a.z] + g_s[b.z] + bb;
        const float eps = fmaf(-0.9998f, uu.z, 0.9999f);
        const float ome = fmaf(0.9998f, uu.z, 0.0001f);
        r.z = eps / fmaf(ome, __expf(-raw), eps);
    }
    {
        const float raw = g_s[a.w] + g_s[b.w] + bb;
        const float eps = fmaf(-0.9998f, uu.w, 0.9999f);
        const float ome = fmaf(0.9998f, uu.w, 0.0001f);
        r.w = eps / fmaf(ome, __expf(-raw), eps);
    }
    reinterpret_cast<float4*>(out)[i] = r;
}

extern "C" void kernel_launch(void* const* d_in, const int* in_sizes, int n_in,
                              void* d_out, int out_size) {
    const float* emb   = (const float*)d_in[0];
    const int*   edges = (const int*)d_in[1];     // int32 (JAX x64 disabled)
    const float* u     = (const float*)d_in[2];
    const float* W     = (const float*)d_in[3];
    const float* b     = (const float*)d_in[4];
    const float* We    = (const float*)d_in[5];
    const float* be    = (const float*)d_in[6];
    float*       out   = (float*)d_out;

    const int nn = in_sizes[0] / IN_DIM;   // 50000
    const int E  = in_sizes[2];            // 800000

    convert_W<<<(IN_DIM * HID / 4 + 255) / 256, 256>>>((const float4*)W);

    cudaFuncSetAttribute(node_kernel, cudaFuncAttributeMaxDynamicSharedMemorySize, SMEM_TOTAL);
    node_kernel<<<(nn + BM - 1) / BM, NTHREADS, SMEM_TOTAL>>>(emb, b, We, nn);

    const int nv = (E >> 2) + 1;
    edge_kernel<<<(nv + 255) / 256, 256>>>(edges, edges + E, u, be, out, E);
}